// round 13
// baseline (speedup 1.0000x reference)
#include <cuda_runtime.h>
#include <stdint.h>

// ---------------- constants ----------------
#define NMAX     131072
#define NBUCKET  16384
#define NT       4          // 2x2 tiles
#define PMAX     2048
#define CANDMAX  4096
#define IMG_W    128
#define IMG_H    128
#define TSZ      64
#define BINS     128        // per tile: 8 x-bins (8px) x 16 y-bins (4px)
#define NSEG     8          // warps (segments) per bin in composite
#define GSTRIDE  ((PMAX + 1) * 3)   // float4s per tile in g_gauss (+1 dummy)

// ---------------- device scratch (static, no allocs; zero-init at load) ----
__device__ int                 g_hist32[NBUCKET];     // 4x8-bit per-tile counts
__device__ unsigned            g_mb[NMAX];            // (mask<<16) | bucket
__device__ int                 g_bcount[NT * NBUCKET];// per-tile prefix / slot ctr
__device__ int                 g_cutoff[NT];
__device__ int                 g_nvalid[NT];
__device__ unsigned long long  g_cand[NT * CANDMAX];
__device__ float4              g_gauss[NT * GSTRIDE];

// ---------------- kernel 1: rect/mask/bucket + packed histogram ------------
__global__ void k_prep(const float2* __restrict__ means,
                       const float4* __restrict__ cov,
                       const float* __restrict__ depths, int N) {
    cudaTriggerProgrammaticLaunchCompletion();
    int i = blockIdx.x * blockDim.x + threadIdx.x;
    if (i >= N) return;
    float4 cv = cov[i];
    float a = cv.x, b = cv.y, c = cv.z, d = cv.w;
    float det = a * d - b * c;
    float mid = 0.5f * (a + d);
    float s   = sqrtf(fmaxf(mid * mid - det, 0.1f));
    float rad = 3.0f * ceilf(sqrtf(fmaxf(mid + s, mid - s)));
    float2 mn = means[i];
    float xmin = fminf(fmaxf(mn.x - rad, 0.f), (float)(IMG_W - 1));
    float xmax = fminf(fmaxf(mn.x + rad, 0.f), (float)(IMG_W - 1));
    float ymin = fminf(fmaxf(mn.y - rad, 0.f), (float)(IMG_H - 1));
    float ymax = fminf(fmaxf(mn.y + rad, 0.f), (float)(IMG_H - 1));
    float dep = depths[i];
    int bucket = min(NBUCKET - 1, max(0, (int)(dep * 1600.0f)));
    unsigned mask = 0, e = 0;
#pragma unroll
    for (int ty = 0; ty < 2; ty++) {
        float hmin = (float)(ty * TSZ), hmax = hmin + (float)(TSZ - 1);
        bool ovy = fminf(ymax, hmax) > fmaxf(ymin, hmin);
#pragma unroll
        for (int tx = 0; tx < 2; tx++) {
            float wmin = (float)(tx * TSZ), wmax = wmin + (float)(TSZ - 1);
            bool ovx = fminf(xmax, wmax) > fmaxf(xmin, wmin);
            if (ovx && ovy) {
                int t = ty * 2 + tx;
                mask |= 1u << t;
                e += 1u << (8 * t);
            }
        }
    }
    if (e) atomicAdd(&g_hist32[bucket], (int)e);
    g_mb[i] = (mask << 16) | (unsigned)bucket;
}

// ---------------- kernel 2: per-tile prefix scan + rank-2048 cutoff --------
__global__ void k_scan() {
    cudaTriggerProgrammaticLaunchCompletion();
    int t = blockIdx.x;
    int* bc = g_bcount + t * NBUCKET;
    __shared__ int warpsum[8];
    __shared__ int s_running, s_cut, s_ctot;
    if (threadIdx.x == 0) { s_running = 0; s_cut = NBUCKET - 1; s_ctot = -1; }
    int lane = threadIdx.x & 31, wid = threadIdx.x >> 5;
    cudaGridDependencySynchronize();           // wait: g_hist32 from k_prep
    __syncthreads();
    for (int base = 0; base < NBUCKET; base += 256) {
        int i = base + threadIdx.x;
        int v = (g_hist32[i] >> (8 * t)) & 0xFF;
        int x = v;
#pragma unroll
        for (int o = 1; o < 32; o <<= 1) {
            int y = __shfl_up_sync(0xffffffffu, x, o);
            if (lane >= o) x += y;
        }
        if (lane == 31) warpsum[wid] = x;
        __syncthreads();
        if (threadIdx.x < 8) {
            int w = warpsum[threadIdx.x];
#pragma unroll
            for (int o = 1; o < 8; o <<= 1) {
                int y = __shfl_up_sync(0xffu, w, o);
                if ((int)threadIdx.x >= o) w += y;
            }
            warpsum[threadIdx.x] = w;
        }
        __syncthreads();
        int incl = x + (wid ? warpsum[wid - 1] : 0);
        int excl = incl - v;
        int run = s_running;
        int gE = run + excl, gI = run + incl;
        bc[i] = gE;                       // exclusive prefix (scatter base)
        if (gE < PMAX && gI >= PMAX) { s_cut = i; s_ctot = gI; }
        __syncthreads();
        if (threadIdx.x == 0) s_running = run + warpsum[7];
        __syncthreads();
        if (s_running >= PMAX) break;     // cutoff found: rest is dead weight
    }
    if (threadIdx.x == 0) {
        int ctot, cut;
        if (s_ctot < 0) { cut = NBUCKET - 1; ctot = s_running; }
        else            { cut = s_cut;       ctot = s_ctot;    }
        g_cutoff[t] = cut;
        g_nvalid[t] = min(PMAX, ctot);
    }
}

// ---------------- kernel 3: scatter candidates (bucket <= cutoff) ----------
__global__ void k_scatter(const float* __restrict__ depths, int N) {
    cudaTriggerProgrammaticLaunchCompletion();
    int i = blockIdx.x * blockDim.x + threadIdx.x;
    cudaGridDependencySynchronize();           // wait: cutoffs (and g_mb, transitively)
    if (i >= N) return;
    unsigned mb = g_mb[i];
    int b = (int)(mb & 0xFFFFu);
    unsigned mask = mb >> 16;
    int c0 = __ldg(&g_cutoff[0]), c1 = __ldg(&g_cutoff[1]);
    int c2 = __ldg(&g_cutoff[2]), c3 = __ldg(&g_cutoff[3]);
    bool p0 = (mask & 1u) && b <= c0;
    bool p1 = (mask & 2u) && b <= c1;
    bool p2 = (mask & 4u) && b <= c2;
    bool p3 = (mask & 8u) && b <= c3;
    if (!(p0 | p1 | p2 | p3)) return;
    unsigned long long key =
        ((unsigned long long)__float_as_uint(__ldg(&depths[i])) << 32) | (unsigned)i;
    if (p0) { int s = atomicAdd(&g_bcount[0 * NBUCKET + b], 1); if (s < CANDMAX) g_cand[0 * CANDMAX + s] = key; }
    if (p1) { int s = atomicAdd(&g_bcount[1 * NBUCKET + b], 1); if (s < CANDMAX) g_cand[1 * CANDMAX + s] = key; }
    if (p2) { int s = atomicAdd(&g_bcount[2 * NBUCKET + b], 1); if (s < CANDMAX) g_cand[2 * CANDMAX + s] = key; }
    if (p3) { int s = atomicAdd(&g_bcount[3 * NBUCKET + b], 1); if (s < CANDMAX) g_cand[3 * CANDMAX + s] = key; }
}

// ---------------- kernel 4: parallel rank + gather/pack --------------------
// One thread per candidate; gather-source loads issued BEFORE the rank loop so
// they overlap the bucket-bound reads. pos = bucket_start + |{smaller keys in
// bucket}| is bit-identical to the stable global argsort (keys unique).
__global__ void k_rankgather(
        const float2* __restrict__ means, const float4* __restrict__ cov,
        const float* __restrict__ color, const float* __restrict__ opac) {
    cudaTriggerProgrammaticLaunchCompletion();
    int t = blockIdx.y;
    int s = blockIdx.x * 256 + threadIdx.x;
    float4* out = g_gauss + t * GSTRIDE;
    if (blockIdx.x == 0 && threadIdx.x == 0) {   // neutral dummy (op = 0):
        out[3 * PMAX + 0] = make_float4(0.f, 0.f, 0.f, 0.f);      // no producer
        out[3 * PMAX + 1] = make_float4(0.f, 0.f, -1000.f, 0.f);  // conflict --
        out[3 * PMAX + 2] = make_float4(0.f, 0.f, 0.f, 0.f);      // pre-sync OK
    }
    cudaGridDependencySynchronize();           // wait: g_cand/g_bcount from scatter
    const int* bc = g_bcount + t * NBUCKET;
    int cut = __ldg(&g_cutoff[t]);
    int ctot = min(__ldg(&bc[cut]), CANDMAX);
    if (s >= ctot) return;
    const unsigned long long* A = g_cand + t * CANDMAX;
    unsigned long long key = __ldg(&A[s]);
    int gi = (int)(unsigned)(key & 0xFFFFFFFFull);
    // issue gather-source loads early (independent of rank computation)
    float4 cv = __ldg(&cov[gi]);
    float2 mn = __ldg(&means[gi]);
    float op = __ldg(&opac[gi]);
    float cr = __ldg(&color[3 * gi]);
    float cg = __ldg(&color[3 * gi + 1]);
    float cb = __ldg(&color[3 * gi + 2]);
    float dep = __uint_as_float((unsigned)(key >> 32));
    int b = min(NBUCKET - 1, max(0, (int)(dep * 1600.0f)));  // == prep's bucket
    int start = b ? __ldg(&bc[b - 1]) : 0;
    int end = min(__ldg(&bc[b]), CANDMAX);
    int rank = 0;
    for (int j = start; j < end; ++j) rank += (__ldg(&A[j]) < key);
    int pos = start + rank;
    if (pos >= PMAX) return;                     // beyond front-most 2048
    float invdet = 1.0f / fmaxf(cv.x * cv.w - cv.y * cv.z, 1e-6f);
    const float S = -0.7213475204444817f;        // -0.5 * log2(e)
    float c00s = S * cv.w * invdet;
    float c11s = S * cv.x * invdet;
    float c01s = -S * (cv.y + cv.z) * invdet;
    out[3 * pos + 0] = make_float4(-mn.x, -mn.y, c00s, c11s);
    out[3 * pos + 1] = make_float4(c01s, op, __log2f(fmaxf(op, 1e-38f)), 0.f);
    out[3 * pos + 2] = make_float4(cr, cg, cb, dep);
}

// ---------------- kernel 5: fused cull + composite, 8 warps per bin --------
// CTA = one 8x4-pixel bin, 8 warps. Each warp composites a contiguous eighth
// of the depth-sorted candidate range (own cull + own local early exit on
// T_w < 1e-5); segments merge exactly via (T,C)∘(T',C') = (T·T', C + T·C').
// Re-zeroes g_hist32 for the next graph replay AFTER the dependency sync
// (post-sync, all earlier readers of g_hist32 are complete).
__global__ void __launch_bounds__(32 * NSEG) k_composite(float* __restrict__ out) {
    __shared__ __align__(16) unsigned short sbuf[NSEG][64];
    __shared__ float sT[NSEG][32];
    __shared__ float sC[NSEG][32][5];

    int wid = threadIdx.x >> 5, lane = threadIdx.x & 31;
    int t = blockIdx.x >> 7, b = blockIdx.x & 127;
    int bx = b & 7, by = b >> 3;
    int px = (t & 1) * TSZ + bx * 8 + (lane & 7);
    int py = (t >> 1) * TSZ + by * 4 + (lane >> 3);
    float pxf = (float)px, pyf = (float)py;
    float x0 = (float)((t & 1) * TSZ + bx * 8), x1 = x0 + 7.f;
    float y0 = (float)((t >> 1) * TSZ + by * 4), y1 = y0 + 3.f;

    cudaGridDependencySynchronize();           // wait: g_gauss from rankgather

    int gtid = blockIdx.x * (32 * NSEG) + threadIdx.x;
    if (gtid < NBUCKET) g_hist32[gtid] = 0;    // prep for next replay

    int nv = g_nvalid[t];
    const float4* gd = g_gauss + t * GSTRIDE;

    // this warp's contiguous segment
    int nvq = (nv + NSEG - 1) / NSEG;
    int w0 = min(nv, wid * nvq);
    int w1 = min(nv, w0 + nvq);

    float T = 1.f, aR = 0.f, aG = 0.f, aB = 0.f, aD = 0.f, aA = 0.f;
    int head = 0, tail = 0;

    for (int base = w0; base < w1; base += 32) {
        int g = base + lane;
        bool keep = false;
        if (g < w1) {
            float4 q0 = __ldg(gd + 3 * g);
            float4 q1 = __ldg(gd + 3 * g + 1);
            float ax = x0 + q0.x, bxx = x1 + q0.x;   // dx interval
            float ay = y0 + q0.y, byy = y1 + q0.y;   // dy interval
            float msx = (ax <= 0.f && bxx >= 0.f) ? 0.f : fminf(ax * ax, bxx * bxx);
            float msy = (ay <= 0.f && byy >= 0.f) ? 0.f : fminf(ay * ay, byy * byy);
            float p1 = ax * ay, p2 = ax * byy, p3 = bxx * ay, p4 = bxx * byy;
            float pmax = fmaxf(fmaxf(p1, p2), fmaxf(p3, p4));
            float pmin = fminf(fminf(p1, p2), fminf(p3, p4));
            float cross = q1.x * ((q1.x > 0.f) ? pmax : pmin);
            float bound = q0.z * msx + q0.w * msy + cross + q1.z;
            keep = bound > -27.f;
        }
        unsigned bal = __ballot_sync(0xffffffffu, keep);
        int pos = head + __popc(bal & ((1u << lane) - 1u));
        if (keep) sbuf[wid][pos & 63] = (unsigned short)g;
        head += __popc(bal);
        __syncwarp();
        while (head - tail >= 4) {
            ushort4 i4 = *reinterpret_cast<const ushort4*>(&sbuf[wid][tail & 63]);
            tail += 4;
#pragma unroll
            for (int u = 0; u < 4; ++u) {
                int idx = (u == 0) ? i4.x : (u == 1) ? i4.y : (u == 2) ? i4.z : i4.w;
                float4 q0 = __ldg(gd + 3 * idx);
                float4 q1 = __ldg(gd + 3 * idx + 1);
                float4 q2 = __ldg(gd + 3 * idx + 2);
                float dx = pxf + q0.x, dy = pyf + q0.y;
                float e = exp2f(fmaf(dx * dy, q1.x, fmaf(dy * dy, q0.w, dx * dx * q0.z)));
                float alpha = fminf(e * q1.y, 0.99f);
                float w = alpha * T;
                aR = fmaf(w, q2.x, aR);
                aG = fmaf(w, q2.y, aG);
                aB = fmaf(w, q2.z, aB);
                aD = fmaf(w, q2.w, aD);
                aA += w;
                T -= w;                              // T *= (1 - alpha) exactly
            }
        }
        if (__all_sync(0xffffffffu, T < 1e-5f)) { tail = head; break; }
    }
    // flush remainder (pad ring with dummy PMAX entries to a multiple of 4)
    if (head - tail) {
        int pad = (4 - ((head - tail) & 3)) & 3;
        if (lane < pad) sbuf[wid][(head + lane) & 63] = (unsigned short)PMAX;
        head += pad;
        __syncwarp();
        while (head - tail >= 4) {
            ushort4 i4 = *reinterpret_cast<const ushort4*>(&sbuf[wid][tail & 63]);
            tail += 4;
#pragma unroll
            for (int u = 0; u < 4; ++u) {
                int idx = (u == 0) ? i4.x : (u == 1) ? i4.y : (u == 2) ? i4.z : i4.w;
                float4 q0 = __ldg(gd + 3 * idx);
                float4 q1 = __ldg(gd + 3 * idx + 1);
                float4 q2 = __ldg(gd + 3 * idx + 2);
                float dx = pxf + q0.x, dy = pyf + q0.y;
                float e = exp2f(fmaf(dx * dy, q1.x, fmaf(dy * dy, q0.w, dx * dx * q0.z)));
                float alpha = fminf(e * q1.y, 0.99f);
                float w = alpha * T;
                aR = fmaf(w, q2.x, aR);
                aG = fmaf(w, q2.y, aG);
                aB = fmaf(w, q2.z, aB);
                aD = fmaf(w, q2.w, aD);
                aA += w;
                T -= w;
            }
        }
    }

    // publish segment partials
    sT[wid][lane] = T;
    sC[wid][lane][0] = aR; sC[wid][lane][1] = aG; sC[wid][lane][2] = aB;
    sC[wid][lane][3] = aD; sC[wid][lane][4] = aA;
    __syncthreads();

    // warp 0: front-to-back merge of the NSEG segments (exact), write output
    if (wid == 0) {
        float Tm = 1.f, R = 0.f, G = 0.f, B = 0.f, D = 0.f, A = 0.f;
#pragma unroll
        for (int w = 0; w < NSEG; ++w) {
            R = fmaf(Tm, sC[w][lane][0], R);
            G = fmaf(Tm, sC[w][lane][1], G);
            B = fmaf(Tm, sC[w][lane][2], B);
            D = fmaf(Tm, sC[w][lane][3], D);
            A = fmaf(Tm, sC[w][lane][4], A);
            Tm *= sT[w][lane];
        }
        int pix = py * IMG_W + px;
        float bg = 1.f - A;
        out[pix * 3 + 0] = R + bg;
        out[pix * 3 + 1] = G + bg;
        out[pix * 3 + 2] = B + bg;
        out[IMG_W * IMG_H * 3 + pix] = D;
        out[IMG_W * IMG_H * 4 + pix] = A;
    }
}

// ---------------- launch (PDL-chained) ----------------
extern "C" void kernel_launch(void* const* d_in, const int* in_sizes, int n_in,
                              void* d_out, int out_size) {
    const float2* means  = (const float2*)d_in[0];
    const float4* cov    = (const float4*)d_in[1];
    const float*  color  = (const float*)d_in[2];
    const float*  opac   = (const float*)d_in[3];
    const float*  depths = (const float*)d_in[4];
    int N = in_sizes[4];

    cudaLaunchAttribute pdl;
    pdl.id = cudaLaunchAttributeProgrammaticStreamSerialization;
    pdl.val.programmaticStreamSerializationAllowed = 1;

    {   // k_prep (head of chain: no PDL attribute)
        cudaLaunchConfig_t cfg = {};
        cfg.gridDim = dim3((N + 255) / 256);
        cfg.blockDim = dim3(256);
        cfg.stream = 0;
        cudaLaunchKernelEx(&cfg, k_prep, means, cov, depths, N);
    }
    {   // k_scan
        cudaLaunchConfig_t cfg = {};
        cfg.gridDim = dim3(NT);
        cfg.blockDim = dim3(256);
        cfg.stream = 0;
        cfg.attrs = &pdl; cfg.numAttrs = 1;
        cudaLaunchKernelEx(&cfg, k_scan);
    }
    {   // k_scatter
        cudaLaunchConfig_t cfg = {};
        cfg.gridDim = dim3((N + 255) / 256);
        cfg.blockDim = dim3(256);
        cfg.stream = 0;
        cfg.attrs = &pdl; cfg.numAttrs = 1;
        cudaLaunchKernelEx(&cfg, k_scatter, depths, N);
    }
    {   // k_rankgather
        cudaLaunchConfig_t cfg = {};
        cfg.gridDim = dim3((CANDMAX + 255) / 256, NT);
        cfg.blockDim = dim3(256);
        cfg.stream = 0;
        cfg.attrs = &pdl; cfg.numAttrs = 1;
        cudaLaunchKernelEx(&cfg, k_rankgather, means, cov, color, opac);
    }
    {   // k_composite
        cudaLaunchConfig_t cfg = {};
        cfg.gridDim = dim3(NT * BINS);
        cfg.blockDim = dim3(32 * NSEG);
        cfg.stream = 0;
        cfg.attrs = &pdl; cfg.numAttrs = 1;
        cudaLaunchKernelEx(&cfg, k_composite, (float*)d_out);
    }
}